// round 17
// baseline (speedup 1.0000x reference)
#include <cuda_runtime.h>
#include <cuda_fp16.h>
#include <cuda_bf16.h>
#include <cstdint>
#include <cstring>

// Problem dims (fixed by the reference)
#define NROWS   16384
#define INDIM   256
#define OUTDIM  128

// Stage-2 tiling
#define BM 128
#define BK 32
#define KT (NROWS / BK)      // 512

// smem (halfs): bufA[4] 128x40, bufB[4] 128(n) x 40  (two tile-pairs)
#define A_BUF_HALFS 5120     // 128 * 40
#define B_BUF_HALFS 5120     // 128 * 40
#define TILE_SMEM ((4 * A_BUF_HALFS + 4 * B_BUF_HALFS) * 2)  // 81920 B
#define RED_SMEM  65536
#define SMEM_AGGR (TILE_SMEM > RED_SMEM ? TILE_SMEM : RED_SMEM)

// Intermediate h TRANSPOSED in fp16: g_hT[o * NROWS + row]
__device__ __half g_hT[(size_t)OUTDIM * NROWS];

// One dynamic-smem declaration for the whole TU.
extern __shared__ char dyn_smem[];

// ---------------------------------------------------------------------------
__device__ __forceinline__ uint32_t smem_u32(const void* p) {
    uint32_t a;
    asm("{ .reg .u64 t; cvta.to.shared.u64 t, %1; cvt.u32.u64 %0, t; }" : "=r"(a) : "l"(p));
    return a;
}
__device__ __forceinline__ uint32_t f2tf32_rn(float f) {
    uint32_t u;
    asm("cvt.rna.tf32.f32 %0, %1;" : "=r"(u) : "f"(f));
    return u;
}
__device__ __forceinline__ void mma_tf32(float c[4], const uint32_t a[4], const uint32_t b[2]) {
    asm volatile(
        "mma.sync.aligned.m16n8k8.row.col.f32.tf32.tf32.f32 "
        "{%0,%1,%2,%3}, {%4,%5,%6,%7}, {%8,%9}, {%0,%1,%2,%3};"
        : "+f"(c[0]), "+f"(c[1]), "+f"(c[2]), "+f"(c[3])
        : "r"(a[0]), "r"(a[1]), "r"(a[2]), "r"(a[3]), "r"(b[0]), "r"(b[1]));
}
__device__ __forceinline__ void mma_f16(float c[4], const uint32_t a[4], const uint32_t b[2]) {
    asm volatile(
        "mma.sync.aligned.m16n8k16.row.col.f32.f16.f16.f32 "
        "{%0,%1,%2,%3}, {%4,%5,%6,%7}, {%8,%9}, {%0,%1,%2,%3};"
        : "+f"(c[0]), "+f"(c[1]), "+f"(c[2]), "+f"(c[3])
        : "r"(a[0]), "r"(a[1]), "r"(a[2]), "r"(a[3]), "r"(b[0]), "r"(b[1]));
}
__device__ __forceinline__ void cp_async16(uint32_t saddr, const void* g) {
    asm volatile("cp.async.cg.shared.global [%0], [%1], 16;" :: "r"(saddr), "l"(g));
}
__device__ __forceinline__ void cp_commit() { asm volatile("cp.async.commit_group;"); }
__device__ __forceinline__ void ldsm_x4(uint32_t r[4], uint32_t saddr) {
    asm volatile("ldmatrix.sync.aligned.m8n8.x4.shared.b16 {%0,%1,%2,%3}, [%4];"
                 : "=r"(r[0]), "=r"(r[1]), "=r"(r[2]), "=r"(r[3]) : "r"(saddr));
}
__device__ __forceinline__ void ldsm_x2(uint32_t r[2], uint32_t saddr) {
    asm volatile("ldmatrix.sync.aligned.m8n8.x2.shared.b16 {%0,%1}, [%2];"
                 : "=r"(r[0]), "=r"(r[1]) : "r"(saddr));
}

// ============================================================================
// Stage 1: h = x @ W^T + b  (tf32, RN both sides) -> g_hT fp16 transposed
// ============================================================================
#define A_STRIDE 36
__global__ __launch_bounds__(256, 1)
void gemm_lin(const float* __restrict__ x, const float* __restrict__ W,
              const float* __restrict__ bias) {
    float* smem = (float*)dyn_smem;
    float* As0 = smem;
    float* As1 = As0 + BM * A_STRIDE;
    float* Ws0 = As1 + BM * A_STRIDE;
    float* Ws1 = Ws0 + OUTDIM * A_STRIDE;

    const int tid  = threadIdx.x;
    const int lane = tid & 31, wid = tid >> 5;
    const int warpM = wid >> 2, warpN = wid & 3;
    const int bm = blockIdx.x;

    uint32_t sA0 = smem_u32(As0), sA1 = smem_u32(As1);
    uint32_t sW0 = smem_u32(Ws0), sW1 = smem_u32(Ws1);

    float c[4][4][4];
#pragma unroll
    for (int i = 0; i < 4; i++)
#pragma unroll
        for (int j = 0; j < 4; j++)
#pragma unroll
            for (int k = 0; k < 4; k++) c[i][j][k] = 0.0f;

    auto load36 = [&](uint32_t sbase, const float* src, int row0, int k0, int ldK) {
#pragma unroll
        for (int t = 0; t < 4; t++) {
            int idx = tid + t * 256;
            int r = idx >> 3, cc = (idx & 7) << 2;
            cp_async16(sbase + (uint32_t)(r * A_STRIDE + cc) * 4u,
                       src + (size_t)(row0 + r) * ldK + k0 + cc);
        }
    };

    load36(sA0, x, bm * BM, 0, INDIM);
    load36(sW0, W, 0, 0, INDIM);
    cp_commit();

    const int KTL = INDIM / BK; // 8
    for (int kt = 0; kt < KTL; kt++) {
        asm volatile("cp.async.wait_group 0;" ::: "memory");
        __syncthreads();
        if (kt + 1 < KTL) {
            load36(((kt + 1) & 1) ? sA1 : sA0, x, bm * BM, (kt + 1) * BK, INDIM);
            load36(((kt + 1) & 1) ? sW1 : sW0, W, 0, (kt + 1) * BK, INDIM);
            cp_commit();
        }
        const float* As = (kt & 1) ? As1 : As0;
        const float* Ws = (kt & 1) ? Ws1 : Ws0;

#pragma unroll
        for (int kk = 0; kk < BK; kk += 8) {
            uint32_t af[4][4];
#pragma unroll
            for (int mi = 0; mi < 4; mi++) {
                int r  = warpM * 64 + mi * 16 + (lane >> 2);
                int cc = kk + (lane & 3);
                af[mi][0] = f2tf32_rn(As[r * A_STRIDE + cc]);
                af[mi][1] = f2tf32_rn(As[(r + 8) * A_STRIDE + cc]);
                af[mi][2] = f2tf32_rn(As[r * A_STRIDE + cc + 4]);
                af[mi][3] = f2tf32_rn(As[(r + 8) * A_STRIDE + cc + 4]);
            }
            uint32_t bf[4][2];
#pragma unroll
            for (int ni = 0; ni < 4; ni++) {
                int n = warpN * 32 + ni * 8 + (lane >> 2);
                int k = kk + (lane & 3);
                bf[ni][0] = f2tf32_rn(Ws[n * A_STRIDE + k]);
                bf[ni][1] = f2tf32_rn(Ws[n * A_STRIDE + k + 4]);
            }
#pragma unroll
            for (int mi = 0; mi < 4; mi++)
#pragma unroll
                for (int ni = 0; ni < 4; ni++) mma_tf32(c[mi][ni], af[mi], bf[ni]);
        }
        __syncthreads();
    }

    // Epilogue: bias add, fp16-RN, transpose via smem, coalesced store to g_hT.
    __half* st = (__half*)dyn_smem;   // st[o * 136 + n]
    __syncthreads();
#pragma unroll
    for (int ni = 0; ni < 4; ni++) {
        int cn = warpN * 32 + ni * 8 + ((lane & 3) << 1);
        float2 bb = *(const float2*)(bias + cn);
#pragma unroll
        for (int mi = 0; mi < 4; mi++) {
            int r = warpM * 64 + mi * 16 + (lane >> 2);
            st[cn * 136 + r]           = __float2half_rn(c[mi][ni][0] + bb.x);
            st[(cn + 1) * 136 + r]     = __float2half_rn(c[mi][ni][1] + bb.y);
            st[cn * 136 + r + 8]       = __float2half_rn(c[mi][ni][2] + bb.x);
            st[(cn + 1) * 136 + r + 8] = __float2half_rn(c[mi][ni][3] + bb.y);
        }
    }
    __syncthreads();
    for (int i = tid; i < 128 * 128; i += 256) {
        int o = i >> 7, n = i & 127;
        g_hT[(size_t)o * NROWS + bm * BM + n] = st[o * 136 + n];
    }
}

// ============================================================================
// Stage 2: out = A_hat @ h, fp16 HMMA m16n8k16.
// 512 threads, 16 warps = 2(M) x 4(N) x 2(K-split). Warp tile 64x32.
// UNROLL-2: two tiles per loop body, 4 A/B buffers, ONE wait+barrier per pair
// (256 sync points instead of 512). Datapath identical to R16:
//   A: LDG fp32 -> regs -> fp16 STS stride-40, fragments via ldmatrix.x4
//   B: cp.async from g_hT into [n][k] smem, fragments via ldmatrix.x2
// ============================================================================
struct ARegs { float4 v[2]; };   // 8 floats: row tid>>2, k (tid&3)*8 .. +7

__device__ __forceinline__ void ldgA(ARegs& ra, const float* __restrict__ A,
                                     int bm, int kt, int tid) {
    const int row = tid >> 2, kc = (tid & 3) * 8;
    const float* p = A + (size_t)(bm * BM + row) * NROWS + kt * BK + kc;
    ra.v[0] = *(const float4*)p;
    ra.v[1] = *(const float4*)(p + 4);
}

__device__ __forceinline__ void stsA(__half* bufA, const ARegs& ra, int tid) {
    const int row = tid >> 2, kc = (tid & 3) * 8;
    const float* f = (const float*)&ra.v[0];
    __half2 h[4];
#pragma unroll
    for (int j = 0; j < 4; j++) h[j] = __floats2half2_rn(f[2 * j], f[2 * j + 1]);
    uint4 u;
    memcpy(&u, h, 16);
    *(uint4*)&bufA[row * 40 + kc] = u;
}

// B tile cp.async: 128 n-rows x 32 k halfs (64 B) from g_hT row o = n.
__device__ __forceinline__ void cpB(uint32_t dstBase, int kt, int tid) {
    const int o = tid >> 2, kq = tid & 3;
    cp_async16(dstBase + (uint32_t)(o * 80 + kq * 16),
               g_hT + (size_t)o * NROWS + kt * BK + kq * 8);
}

__device__ __forceinline__ void computeTile(uint32_t saBase, uint32_t sbBase,
                                            float c[4][4][4], int lane,
                                            int warpM, int warpN, int warpK) {
    const int rbase = warpM * 64 + ((lane >> 3) & 1) * 8 + (lane & 7);
    const int kloc  = warpK * 16 + (lane >> 4) * 8;
    uint32_t af[4][4];
#pragma unroll
    for (int mi = 0; mi < 4; mi++) {
        uint32_t sa = saBase + (uint32_t)(((rbase + mi * 16) * 40 + kloc) * 2);
        ldsm_x4(af[mi], sa);
    }
    const int nrow = (lane & 7);
    const int hsel = (lane >> 3) & 1;
    uint32_t bf[4][2];
#pragma unroll
    for (int ni = 0; ni < 4; ni++) {
        int n = warpN * 32 + ni * 8 + nrow;
        uint32_t sb = sbBase + (uint32_t)(n * 80 + warpK * 32 + hsel * 16);
        ldsm_x2(bf[ni], sb);
    }
#pragma unroll
    for (int mi = 0; mi < 4; mi++)
#pragma unroll
        for (int ni = 0; ni < 4; ni++) mma_f16(c[mi][ni], af[mi], bf[ni]);
}

__global__ __launch_bounds__(512, 1)
void gemm_aggr(const float* __restrict__ A, float* __restrict__ out) {
    __half* sm = (__half*)dyn_smem;
    uint32_t sa[4], sb[4];
#pragma unroll
    for (int s = 0; s < 4; s++) {
        sa[s] = smem_u32(sm + s * A_BUF_HALFS);
        sb[s] = smem_u32(sm + 4 * A_BUF_HALFS + s * B_BUF_HALFS);
    }
    __half* bufA[4];
#pragma unroll
    for (int s = 0; s < 4; s++) bufA[s] = sm + s * A_BUF_HALFS;

    const int tid  = threadIdx.x;
    const int lane = tid & 31, wid = tid >> 5;     // wid 0..15
    const int warpK = wid >> 3;                    // 0,1
    const int warpM = (wid >> 2) & 1;              // 0,1
    const int warpN = wid & 3;                     // 0..3
    const int bm = blockIdx.x;

    float c[4][4][4];
#pragma unroll
    for (int i = 0; i < 4; i++)
#pragma unroll
        for (int j = 0; j < 4; j++)
#pragma unroll
            for (int k = 0; k < 4; k++) c[i][j][k] = 0.0f;

    // Prologue: tiles 0,1 into slot pair {0,1}.
    ARegs ra;
    {
        cpB(sb[0], 0, tid);
        cpB(sb[1], 1, tid);
        cp_commit();
        ldgA(ra, A, bm, 0, tid);
        stsA(bufA[0], ra, tid);
        ldgA(ra, A, bm, 1, tid);
        stsA(bufA[1], ra, tid);
        asm volatile("cp.async.wait_group 0;" ::: "memory");
        __syncthreads();
    }

    const int KT2 = KT / 2;   // 256 pair-iterations
    for (int i = 0; i < KT2; i++) {
        const int s = (i & 1) << 1;      // current slot pair base (0 or 2)
        const int o = 2 - s;             // other slot pair base
        const int t2 = (2 * i + 2 < KT) ? 2 * i + 2 : KT - 2;
        const int t3 = (2 * i + 3 < KT) ? 2 * i + 3 : KT - 1;

        // Prefetch next pair's B tiles (completion checked at pair end).
        cpB(sb[o],     t2, tid);
        cpB(sb[o + 1], t3, tid);
        cp_commit();

        // A tile t2: LDG now, STS after first compute (latency covered).
        ldgA(ra, A, bm, t2, tid);
        computeTile(sa[s], sb[s], c, lane, warpM, warpN, warpK);       // tile 2i
        stsA(bufA[o], ra, tid);

        // A tile t3: LDG now, STS after second compute.
        ldgA(ra, A, bm, t3, tid);
        computeTile(sa[s + 1], sb[s + 1], c, lane, warpM, warpN, warpK); // tile 2i+1
        stsA(bufA[o + 1], ra, tid);

        // Single sync point per pair.
        asm volatile("cp.async.wait_group 0;" ::: "memory");
        __syncthreads();
    }

    // ---- split-K reduction: warpK=1 -> smem, warpK=0 adds & stores ----
    float* red = (float*)dyn_smem;        // 8 warps * 2048 floats = 64 KB
    float4* cf4 = (float4*)&c[0][0][0];   // 16 float4 per thread
    __syncthreads();
    if (warpK == 1) {
        float4* dst = (float4*)(red + (wid - 8) * 2048);
#pragma unroll
        for (int i = 0; i < 16; i++) dst[i * 32 + lane] = cf4[i];
    }
    __syncthreads();
    if (warpK == 0) {
        const float4* src = (const float4*)(red + wid * 2048);
#pragma unroll
        for (int i = 0; i < 16; i++) {
            float4 v = src[i * 32 + lane];
            cf4[i].x += v.x; cf4[i].y += v.y; cf4[i].z += v.z; cf4[i].w += v.w;
        }
#pragma unroll
        for (int mi = 0; mi < 4; mi++)
#pragma unroll
            for (int ni = 0; ni < 4; ni++) {
                int r  = bm * BM + warpM * 64 + mi * 16 + (lane >> 2);
                int cn = warpN * 32 + ni * 8 + ((lane & 3) << 1);
                *(float2*)&out[(size_t)r * OUTDIM + cn] =
                    make_float2(c[mi][ni][0], c[mi][ni][1]);
                *(float2*)&out[(size_t)(r + 8) * OUTDIM + cn] =
                    make_float2(c[mi][ni][2], c[mi][ni][3]);
            }
    }
}

static const int SMEM_LIN = (2 * BM * A_STRIDE + 2 * OUTDIM * A_STRIDE) * 4;  // 73728

extern "C" void kernel_launch(void* const* d_in, const int* in_sizes, int n_in,
                              void* d_out, int out_size) {
    const float* x     = (const float*)d_in[0];
    const float* A_hat = (const float*)d_in[1];
    const float* W     = (const float*)d_in[2];
    const float* b     = (const float*)d_in[3];
    float* out = (float*)d_out;

    cudaFuncSetAttribute(gemm_lin,  cudaFuncAttributeMaxDynamicSharedMemorySize, SMEM_LIN);
    cudaFuncSetAttribute(gemm_aggr, cudaFuncAttributeMaxDynamicSharedMemorySize, SMEM_AGGR);

    gemm_lin<<<NROWS / BM, 256, SMEM_LIN>>>(x, W, b);
    gemm_aggr<<<NROWS / BM, 512, SMEM_AGGR>>>(A_hat, out);
}